// round 10
// baseline (speedup 1.0000x reference)
#include <cuda_runtime.h>

// Soft quantizer forward == hard nearest-level quantization (straight-through).
// levels[k] = -1 + k*(2/24), k = 0..24.
//
// HBM-streaming kernel at the DRAM roofline (~7.1 TB/s effective, ~89% of
// spec). Memory shape (best of R2-R8 sweep): per tile, 8 front-batched
// __ldcg float4 loads (L2-cached, L1-bypass) + 8 __stcs (evict-first)
// stores, 256 threads/block. Persistent grid sized so every block does
// EXACTLY ntiles/blocks tiles (uniform work), one resident wave on the
// 152-SM GB300.

#define Z_MIN   (-1.0f)
#define STEP    (2.0f / 24.0f)
#define INVSTEP (12.0f)
#define LMAX    (24.0f)

__device__ __forceinline__ float quant1(float x) {
    float k = rintf((x - Z_MIN) * INVSTEP);
    k = fminf(fmaxf(k, 0.0f), LMAX);
    return fmaf(k, STEP, Z_MIN);
}

__device__ __forceinline__ float4 quant4(float4 a) {
    float4 r;
    r.x = quant1(a.x); r.y = quant1(a.y); r.z = quant1(a.z); r.w = quant1(a.w);
    return r;
}

#define TILE 8                  // float4s per thread per tile (128B)
#define NTHR 256                // threads per block
#define TILE_F4 (NTHR * TILE)   // float4s per tile = 2048

__global__ void __launch_bounds__(NTHR) quant_kernel_pers(const float4* __restrict__ in,
                                                          float4* __restrict__ out,
                                                          int n4, int ntiles) {
    for (int t = blockIdx.x; t < ntiles; t += gridDim.x) {
        int base = t * TILE_F4 + threadIdx.x;

        if (base + (TILE - 1) * NTHR < n4) {
            // fast path: full tile in range (all tiles except possibly the last)
            float4 v[TILE];
            #pragma unroll
            for (int j = 0; j < TILE; j++) v[j] = __ldcg(&in[base + j * NTHR]);
            #pragma unroll
            for (int j = 0; j < TILE; j++) v[j] = quant4(v[j]);
            #pragma unroll
            for (int j = 0; j < TILE; j++) __stcs(&out[base + j * NTHR], v[j]);
        } else {
            #pragma unroll
            for (int j = 0; j < TILE; j++) {
                int i = base + j * NTHR;
                if (i < n4) __stcs(&out[i], quant4(__ldcg(&in[i])));
            }
        }
    }
}

__global__ void __launch_bounds__(256) quant_kernel_tail(const float* __restrict__ in,
                                                         float* __restrict__ out,
                                                         int start, int n) {
    int i = start + blockIdx.x * blockDim.x + threadIdx.x;
    if (i < n) out[i] = quant1(in[i]);
}

extern "C" void kernel_launch(void* const* d_in, const int* in_sizes, int n_in,
                              void* d_out, int out_size) {
    const float* x = (const float*)d_in[0];
    float* out = (float*)d_out;
    int n = in_sizes[0];

    int n4 = n / 4;
    int tail_start = n4 * 4;

    if (n4 > 0) {
        int ntiles = (n4 + TILE_F4 - 1) / TILE_F4;   // 2048 for this shape

        // Pick a block count that divides ntiles evenly (uniform per-block
        // work) while staying within ~1 resident wave on 152 SMs (<=1024
        // blocks at 6 CTAs/SM for this reg count). For ntiles=2048 -> 1024.
        int blocks = ntiles;
        while (blocks > 1024) blocks = (blocks + 1) / 2;   // halve (2048->1024 etc.)
        if (blocks < 1) blocks = 1;

        quant_kernel_pers<<<blocks, NTHR>>>((const float4*)x, (float4*)out, n4, ntiles);
    }
    if (tail_start < n) {
        int rem = n - tail_start;
        int threads = 256;
        int blocks = (rem + threads - 1) / threads;
        quant_kernel_tail<<<blocks, threads>>>(x, out, tail_start, n);
    }
}

// round 11
// speedup vs baseline: 1.0358x; 1.0358x over previous
#include <cuda_runtime.h>

// Soft quantizer forward == hard nearest-level quantization (straight-through).
// levels[k] = -1 + k*(2/24), k = 0..24.
//
// Final form: HBM-streaming kernel at the DRAM roofline (~7.1 TB/s
// effective, ~89% of the 8 TB/s spec). Measured-best configuration from the
// R2-R9 sweep: persistent grid-stride kernel, 256 threads/block, TILE=8
// float4 per thread per tile (128B), 8 front-batched __ldcg loads
// (L2-cached, L1-bypass) + 8 __stcs (evict-first) streaming stores.
// Persistent wave sized for GB300's 152 SMs at 5 resident CTAs/SM.

#define Z_MIN   (-1.0f)
#define STEP    (2.0f / 24.0f)
#define INVSTEP (12.0f)
#define LMAX    (24.0f)

__device__ __forceinline__ float quant1(float x) {
    float k = rintf((x - Z_MIN) * INVSTEP);
    k = fminf(fmaxf(k, 0.0f), LMAX);
    return fmaf(k, STEP, Z_MIN);
}

__device__ __forceinline__ float4 quant4(float4 a) {
    float4 r;
    r.x = quant1(a.x); r.y = quant1(a.y); r.z = quant1(a.z); r.w = quant1(a.w);
    return r;
}

#define TILE 8                  // float4s per thread per tile (128B)
#define NTHR 256                // threads per block
#define TILE_F4 (NTHR * TILE)   // float4s per tile = 2048

__global__ void __launch_bounds__(NTHR) quant_kernel_pers(const float4* __restrict__ in,
                                                          float4* __restrict__ out,
                                                          int n4, int ntiles) {
    for (int t = blockIdx.x; t < ntiles; t += gridDim.x) {
        int base = t * TILE_F4 + threadIdx.x;

        if (base + (TILE - 1) * NTHR < n4) {
            // fast path: full tile in range (all tiles except possibly the last)
            float4 v[TILE];
            #pragma unroll
            for (int j = 0; j < TILE; j++) v[j] = __ldcg(&in[base + j * NTHR]);
            #pragma unroll
            for (int j = 0; j < TILE; j++) v[j] = quant4(v[j]);
            #pragma unroll
            for (int j = 0; j < TILE; j++) __stcs(&out[base + j * NTHR], v[j]);
        } else {
            #pragma unroll
            for (int j = 0; j < TILE; j++) {
                int i = base + j * NTHR;
                if (i < n4) __stcs(&out[i], quant4(__ldcg(&in[i])));
            }
        }
    }
}

__global__ void __launch_bounds__(256) quant_kernel_tail(const float* __restrict__ in,
                                                         float* __restrict__ out,
                                                         int start, int n) {
    int i = start + blockIdx.x * blockDim.x + threadIdx.x;
    if (i < n) out[i] = quant1(in[i]);
}

extern "C" void kernel_launch(void* const* d_in, const int* in_sizes, int n_in,
                              void* d_out, int out_size) {
    const float* x = (const float*)d_in[0];
    float* out = (float*)d_out;
    int n = in_sizes[0];

    int n4 = n / 4;
    int tail_start = n4 * 4;

    if (n4 > 0) {
        int ntiles = (n4 + TILE_F4 - 1) / TILE_F4;   // 2048 for this shape
        int blocks = 152 * 5;                        // one full resident wave (GB300: 152 SMs)
        if (blocks > ntiles) blocks = ntiles;
        quant_kernel_pers<<<blocks, NTHR>>>((const float4*)x, (float4*)out, n4, ntiles);
    }
    if (tail_start < n) {
        int rem = n - tail_start;
        int threads = 256;
        int blocks = (rem + threads - 1) / threads;
        quant_kernel_tail<<<blocks, threads>>>(x, out, tail_start, n);
    }
}